// round 11
// baseline (speedup 1.0000x reference)
#include <cuda_runtime.h>
#include <cuda_fp16.h>
#include <cstdint>

#define IN_DIM  256
#define OUT_DIM 128
#define B_ROWS  4096
#define N_COLS  8192
#define ALPHA   0.2f
#define NSPLIT  8
#define NCHUNK  (N_COLS / NSPLIT)  // 1024 n per CTA
#define KT      32                 // n per K-tile
#define NT      (NCHUNK / KT)      // 32 tiles

// ---------------- device scratch (static, allocation-free) ----------------
__device__ __align__(16) __half g_hb[N_COLS * OUT_DIM]; // [8192 n][128 f] fp16
__device__ float g_s2[N_COLS];
__device__ float g_p[N_COLS];
__device__ float g_q[N_COLS];
__device__ float g_t[B_ROWS];   // -s1[b]
__device__ float g_P[B_ROWS];
__device__ float g_Q[B_ROWS];
__device__ unsigned int g_s2max_bits;                   // order-mapped float max
__device__ __align__(16) float g_part[(size_t)NSPLIT * B_ROWS * OUT_DIM]; // 16 MB

// ---------------- helpers ----------------
__device__ __forceinline__ uint32_t smem_u32(const void* p) {
    uint32_t a;
    asm("{ .reg .u64 t; cvta.to.shared.u64 t, %1; cvt.u32.u64 %0, t; }"
        : "=r"(a) : "l"(p));
    return a;
}
__device__ __forceinline__ void cpa16(uint32_t s, const void* g) {
    asm volatile("cp.async.cg.shared.global [%0], [%1], 16;" :: "r"(s), "l"(g));
}
__device__ __forceinline__ void sts32(uint32_t a, uint32_t v) {
    asm volatile("st.shared.b32 [%0], %1;" :: "r"(a), "r"(v));
}
__device__ __forceinline__ void ldsm4(uint32_t* r, uint32_t a) {
    asm volatile("ldmatrix.sync.aligned.m8n8.x4.shared.b16 {%0,%1,%2,%3}, [%4];"
                 : "=r"(r[0]), "=r"(r[1]), "=r"(r[2]), "=r"(r[3]) : "r"(a));
}
__device__ __forceinline__ void ldsm4t(uint32_t* r, uint32_t a) {
    asm volatile("ldmatrix.sync.aligned.m8n8.x4.trans.shared.b16 {%0,%1,%2,%3}, [%4];"
                 : "=r"(r[0]), "=r"(r[1]), "=r"(r[2]), "=r"(r[3]) : "r"(a));
}
__device__ __forceinline__ void mma_f16(float* d, const uint32_t* a,
                                        uint32_t b0, uint32_t b1) {
    asm volatile(
        "mma.sync.aligned.m16n8k16.row.col.f32.f16.f16.f32 "
        "{%0,%1,%2,%3},{%4,%5,%6,%7},{%8,%9},{%0,%1,%2,%3};"
        : "+f"(d[0]), "+f"(d[1]), "+f"(d[2]), "+f"(d[3])
        : "r"(a[0]), "r"(a[1]), "r"(a[2]), "r"(a[3]), "r"(b0), "r"(b1));
}
// order-preserving float <-> uint map
__device__ __forceinline__ unsigned int f2key(float f) {
    int i = __float_as_int(f);
    return (i >= 0) ? ((unsigned)i ^ 0x80000000u) : ~(unsigned)i;
}
__device__ __forceinline__ float key2f(unsigned int k) {
    int i = (k & 0x80000000u) ? (int)(k ^ 0x80000000u) : (int)~k;
    return __int_as_float(i);
}

// ---------------- K1: k_prep — Wa1 (local), s1 -> g_t ----------------
__global__ __launch_bounds__(256) void k_prep(const float* __restrict__ gf,
                                              const int* __restrict__ nodes,
                                              const float* __restrict__ W,
                                              const float* __restrict__ a1) {
    __shared__ float sWa1[IN_DIM];
    int t = threadIdx.x, lane = t & 31, wid = t >> 5;
    if (blockIdx.x == 0 && t == 0) g_s2max_bits = 0u;
    {
        const float* row = W + t * OUT_DIM;
        float s = 0.f;
#pragma unroll 8
        for (int c = 0; c < OUT_DIM; c++) s += row[c] * a1[c];
        sWa1[t] = s;
    }
    __syncthreads();
#pragma unroll
    for (int rr = 0; rr < 4; rr++) {
        int b = blockIdx.x * 32 + wid * 4 + rr;
        const float* row = gf + (size_t)nodes[b] * IN_DIM;
        float s = 0.f;
#pragma unroll
        for (int k = lane; k < IN_DIM; k += 32) s += row[k] * sWa1[k];
#pragma unroll
        for (int o = 16; o; o >>= 1) s += __shfl_xor_sync(0xffffffffu, s, o);
        if (lane == 0) g_t[b] = -s;
    }
}

// ---------------- K2: k_hneigh — pipelined h = gf[un]@W; s2, max ----------
__global__ __launch_bounds__(256) void k_hneigh(
    const float* __restrict__ gf, const int* __restrict__ un,
    const float* __restrict__ W, const float* __restrict__ a2) {
    __shared__ __align__(16) float As[2][32][36];
    __shared__ __align__(16) float Ws[2][32][132];
    int t = threadIdx.x, lane = t & 31, wid = t >> 5;
    int r0 = blockIdx.x * 32;

    const int arow = t >> 3, ach = t & 7;
    const float* asrc = gf + (size_t)un[r0 + arow] * IN_DIM + ach * 4;
    uint32_t adst[2] = {smem_u32(&As[0][arow][ach * 4]),
                        smem_u32(&As[1][arow][ach * 4])};
    uint32_t wdst[2][4];
    const float* wsrc[4];
#pragma unroll
    for (int u = 0; u < 4; u++) {
        int idx = t * 4 + u, wrow = idx >> 5, wch = idx & 31;
        wsrc[u] = W + (size_t)wrow * OUT_DIM + wch * 4;
        wdst[0][u] = smem_u32(&Ws[0][wrow][wch * 4]);
        wdst[1][u] = smem_u32(&Ws[1][wrow][wch * 4]);
    }

    cpa16(adst[0], asrc);
#pragma unroll
    for (int u = 0; u < 4; u++) cpa16(wdst[0][u], wsrc[u]);
    asm volatile("cp.async.commit_group;");

    float acc[4][4] = {};
    for (int kb = 0; kb < 8; kb++) {
        const int cur = kb & 1;
        if (kb + 1 < 8) {
            cpa16(adst[cur ^ 1], asrc + (kb + 1) * 32);
#pragma unroll
            for (int u = 0; u < 4; u++)
                cpa16(wdst[cur ^ 1][u], wsrc[u] + (size_t)(kb + 1) * 32 * OUT_DIM);
            asm volatile("cp.async.commit_group;");
            asm volatile("cp.async.wait_group 1;");
        } else {
            asm volatile("cp.async.wait_group 0;");
        }
        __syncthreads();
#pragma unroll
        for (int kk = 0; kk < 32; kk++) {
            float4 wv = *(const float4*)&Ws[cur][kk][4 * lane];
            float wvv[4] = {wv.x, wv.y, wv.z, wv.w};
            float av[4];
#pragma unroll
            for (int i = 0; i < 4; i++) av[i] = As[cur][wid + 8 * i][kk];
#pragma unroll
            for (int i = 0; i < 4; i++)
#pragma unroll
                for (int c = 0; c < 4; c++) acc[i][c] += av[i] * wvv[c];
        }
        __syncthreads();
    }

    float4 a2v = *(const float4*)&a2[4 * lane];
    float wmax = -1e30f;
#pragma unroll
    for (int i = 0; i < 4; i++) {
        int r = r0 + wid + 8 * i;
        float part = acc[i][0] * a2v.x + acc[i][1] * a2v.y +
                     acc[i][2] * a2v.z + acc[i][3] * a2v.w;
#pragma unroll
        for (int o = 16; o; o >>= 1) part += __shfl_xor_sync(0xffffffffu, part, o);
        if (lane == 0) {
            g_s2[r] = part;
            wmax = fmaxf(wmax, part);
        }
        __half2 h01 = __floats2half2_rn(acc[i][0], acc[i][1]);
        __half2 h23 = __floats2half2_rn(acc[i][2], acc[i][3]);
        __half2* dst = (__half2*)(g_hb + (size_t)r * OUT_DIM + 4 * lane);
        dst[0] = h01;
        dst[1] = h23;
    }
    if (lane == 0) atomicMax(&g_s2max_bits, f2key(wmax));
}

// ---------------- K2b: k_pq — p/q per n, P/Q per row (true S2max) ----------
__global__ __launch_bounds__(256) void k_pq() {
    const float M = key2f(g_s2max_bits);
    int idx = blockIdx.x * 256 + threadIdx.x;
    if (idx < N_COLS) {
        float d = g_s2[idx] - M;
        g_p[idx] = expf(d);
        g_q[idx] = expf(ALPHA * d);
    } else {
        int b = idx - N_COLS;
        float s1 = -g_t[b];
        float v = s1 + M;
        float mh = fmaxf(v, ALPHA * v);
        g_P[b] = expf(v - mh);
        g_Q[b] = expf(ALPHA * v - mh);
    }
}

// ---------------- K3: k_main — pipelined HMMA weighted sum -----------------
// CTA 256 thr (8 warps), tile 64b x 128f, n-chunk 1024, 32 K-tiles of 32 n.
// Warp grid: bwarp = wid>>2 (2 x 32b), fwarp = wid&3 (4 x 32f); acc 32/thread.
// Rings: Wt x3 (64x80B), Ht x3 (32x272B). ONE __syncthreads per tile.
// Iteration t: stage(t+2)->regs | wgen(t+1)->Wt[(t+1)%3] | wait h(t) | sync |
//              commit h(t+2)->Ht[(t+2)%3] | MMA(t).
__global__ __launch_bounds__(256, 3) void k_main(const int* __restrict__ mask) {
    extern __shared__ __align__(16) char dsm[];
    const uint32_t sb = smem_u32(dsm);
    const uint32_t Wt0 = sb;               // + k*5120, k<3
    const uint32_t Ht0 = sb + 15360;       // + k*8704, k<3
    float* sT = (float*)(dsm + 41472);
    float* sP = sT + 64;
    float* sQ = sP + 64;

    const int tid = threadIdx.x, lane = tid & 31, wid = tid >> 5;
    const int qr = lane >> 2, qc = lane & 3;
    const int bwarp = wid >> 2, fwarp = wid & 3;
    const int gb0 = blockIdx.x * 64;
    const int nbase = blockIdx.y * NCHUNK;

    if (tid < 64) {
        sT[tid] = g_t[gb0 + tid];
        sP[tid] = g_P[gb0 + tid];
        sQ[tid] = g_Q[gb0 + tid];
    }

    // wgen mapping: warp -> rows [wid*8, wid*8+8); bsub halves, np = n-pair
    const int bsub = lane >> 4, np = lane & 15;
    const int r0w = wid * 8 + bsub * 4;    // this lane's 4 rows
    const int* mrow = mask + (size_t)(gb0 + r0w) * N_COLS + nbase + 2 * np;
    const uint32_t wg0 = (uint32_t)r0w * 80 + np * 4;

    // h cp.async mapping: row = tid>>3 (32 n-rows), 8 threads x 32B per row
    const int hrow = tid >> 3, hc8 = tid & 7;
    const uint32_t hst = (uint32_t)hrow * 272 + hc8 * 32;
    const __half* hsrc = g_hb + (size_t)(nbase + hrow) * OUT_DIM + hc8 * 16;

    // ldmatrix per-lane offsets
    const uint32_t lrow = (lane & 7) + ((lane >> 3) & 1) * 8;
    const uint32_t akoff = ((lane >> 4) & 1) * 16;
    const uint32_t arow_off = lrow * 80 + akoff;
    const uint32_t brow_off = lrow * 272 + akoff;

    // register staging: set[k&1] holds tile k's mask + n-scalars
    int2 mi[2][4];
    float2 pp[2], qq[2], ss[2];
#pragma unroll
    for (int k = 0; k < 2; k++) {
        const int* m2 = mrow + k * KT;
#pragma unroll
        for (int i = 0; i < 4; i++) mi[k][i] = *(const int2*)(m2 + (size_t)i * N_COLS);
        int n0 = nbase + k * KT + 2 * np;
        pp[k] = *(const float2*)&g_p[n0];
        qq[k] = *(const float2*)&g_q[n0];
        ss[k] = *(const float2*)&g_s2[n0];
    }
    // h(0), h(1) in flight
    cpa16(Ht0 + hst, hsrc);
    cpa16(Ht0 + hst + 16, hsrc + 8);
    asm volatile("cp.async.commit_group;");
    cpa16(Ht0 + 8704 + hst, hsrc + KT * OUT_DIM);
    cpa16(Ht0 + 8704 + hst + 16, hsrc + KT * OUT_DIM + 8);
    asm volatile("cp.async.commit_group;");

    float d[2][4][4];
#pragma unroll
    for (int mb = 0; mb < 2; mb++)
#pragma unroll
        for (int fb = 0; fb < 4; fb++)
#pragma unroll
            for (int c = 0; c < 4; c++) d[mb][fb][c] = 0.f;

    __syncthreads();  // sT/sP/sQ visible

    // wgen(0) -> Wt[0] (uses set[0]; consumed before iter0 overwrites it)
    {
        uint32_t wa = Wt0 + wg0;
#pragma unroll
        for (int i = 0; i < 4; i++) {
            int b = r0w + i;
            float w0 = 0.f, w1 = 0.f;
            if (mi[0][i].x) w0 = (ss[0].x >= sT[b]) ? sP[b] * pp[0].x : sQ[b] * qq[0].x;
            if (mi[0][i].y) w1 = (ss[0].y >= sT[b]) ? sP[b] * pp[0].y : sQ[b] * qq[0].y;
            __half2 h2 = __floats2half2_rn(w0, w1);
            sts32(wa, *(uint32_t*)&h2);
            wa += 80;
        }
    }

    for (int t = 0; t < NT; t++) {
        // stage tile t+2 into set[t&1]
        if (t + 2 < NT) {
            const int* m2 = mrow + (t + 2) * KT;
#pragma unroll
            for (int i = 0; i < 4; i++)
                mi[t & 1][i] = *(const int2*)(m2 + (size_t)i * N_COLS);
            int n0 = nbase + (t + 2) * KT + 2 * np;
            pp[t & 1] = *(const float2*)&g_p[n0];
            qq[t & 1] = *(const float2*)&g_q[n0];
            ss[t & 1] = *(const float2*)&g_s2[n0];
        }
        // wgen(t+1) from set[(t+1)&1] -> Wt[(t+1)%3]
        if (t + 1 < NT) {
            const int s = (t + 1) & 1;
            uint32_t wa = Wt0 + ((t + 1) % 3) * 5120 + wg0;
#pragma unroll
            for (int i = 0; i < 4; i++) {
                int b = r0w + i;
                float w0 = 0.f, w1 = 0.f;
                if (mi[s][i].x) w0 = (ss[s].x >= sT[b]) ? sP[b] * pp[s].x : sQ[b] * qq[s].x;
                if (mi[s][i].y) w1 = (ss[s].y >= sT[b]) ? sP[b] * pp[s].y : sQ[b] * qq[s].y;
                __half2 h2 = __floats2half2_rn(w0, w1);
                sts32(wa, *(uint32_t*)&h2);
                wa += 80;
            }
        }
        // ensure h(t) arrived (FIFO: <=1 pending => oldest pending is t+1)
        if (t + 1 < NT) asm volatile("cp.async.wait_group 1;");
        else            asm volatile("cp.async.wait_group 0;");
        __syncthreads();

        // prefetch h(t+2) -> Ht[(t+2)%3] (its last reader MMA(t-1) pre-sync)
        if (t + 2 < NT) {
            uint32_t hd = Ht0 + ((t + 2) % 3) * 8704 + hst;
            const __half* src = hsrc + (t + 2) * KT * OUT_DIM;
            cpa16(hd, src);
            cpa16(hd + 16, src + 8);
            asm volatile("cp.async.commit_group;");
        }

        // MMA(t): Wt[t%3], Ht[t%3]; 8 LDSM + 16 HMMA per warp
        const uint32_t Wb = Wt0 + (t % 3) * 5120 + bwarp * 32 * 80 + arow_off;
        const uint32_t Hb = Ht0 + (t % 3) * 8704 + fwarp * 64 + brow_off;
#pragma unroll
        for (int j = 0; j < 2; j++) {
            uint32_t a0[4], a1[4];
            ldsm4(a0, Wb + j * 32);
            ldsm4(a1, Wb + j * 32 + 16 * 80);
#pragma unroll
            for (int P = 0; P < 2; P++) {
                uint32_t b4[4];
                ldsm4t(b4, Hb + j * 16 * 272 + P * 32);
                mma_f16(d[0][2 * P], a0, b4[0], b4[1]);
                mma_f16(d[1][2 * P], a1, b4[0], b4[1]);
                mma_f16(d[0][2 * P + 1], a0, b4[2], b4[3]);
                mma_f16(d[1][2 * P + 1], a1, b4[2], b4[3]);
            }
        }
    }

    // epilogue: write partials
    float* pbase = g_part + (size_t)blockIdx.y * B_ROWS * OUT_DIM;
#pragma unroll
    for (int mb = 0; mb < 2; mb++) {
        int br = gb0 + bwarp * 32 + mb * 16 + qr;
#pragma unroll
        for (int fb = 0; fb < 4; fb++) {
            int f = fwarp * 32 + fb * 8 + qc * 2;
            float* p0 = pbase + (size_t)br * OUT_DIM + f;
            *(float2*)p0 = make_float2(d[mb][fb][0], d[mb][fb][1]);
            *(float2*)(p0 + 8 * OUT_DIM) = make_float2(d[mb][fb][2], d[mb][fb][3]);
        }
    }
}

// ---------------- K4: reduce partials + L2 normalize ----------------
__global__ __launch_bounds__(128) void k_finish(float* __restrict__ out) {
    __shared__ float red[4];
    int b = blockIdx.x, f = threadIdx.x;
    float s = 0.f;
#pragma unroll
    for (int k = 0; k < NSPLIT; k++)
        s += g_part[((size_t)k * B_ROWS + b) * OUT_DIM + f];
    float ss = s * s;
#pragma unroll
    for (int o = 16; o; o >>= 1) ss += __shfl_xor_sync(0xffffffffu, ss, o);
    if ((f & 31) == 0) red[f >> 5] = ss;
    __syncthreads();
    float tot = red[0] + red[1] + red[2] + red[3];
    out[b * OUT_DIM + f] = s / fmaxf(sqrtf(tot), 1e-12f);
}

// ---------------- launch ----------------
extern "C" void kernel_launch(void* const* d_in, const int* in_sizes, int n_in,
                              void* d_out, int out_size) {
    const float* gf    = (const float*)d_in[0];  // [100000, 256]
    const int*   nodes = (const int*)d_in[1];    // [4096]
    const int*   un    = (const int*)d_in[2];    // [8192]
    const int*   mask  = (const int*)d_in[3];    // [4096, 8192]
    const float* W     = (const float*)d_in[4];  // [256, 128]
    const float* a1    = (const float*)d_in[5];  // [128]
    const float* a2    = (const float*)d_in[6];  // [128]
    float* out = (float*)d_out;                  // [4096, 128]

    static int smem_set = 0;
    const int SMEM = 41472 + 3 * 64 * 4;  // 3xWt + 3xHt + sT/sP/sQ = 42240
    if (!smem_set) {
        cudaFuncSetAttribute(k_main, cudaFuncAttributeMaxDynamicSharedMemorySize, SMEM);
        smem_set = 1;
    }

    k_prep<<<B_ROWS / 32, 256>>>(gf, nodes, W, a1);
    k_hneigh<<<N_COLS / 32, 256>>>(gf, un, W, a2);
    k_pq<<<(N_COLS + B_ROWS) / 256, 256>>>();
    k_main<<<dim3(B_ROWS / 64, NSPLIT), 256, SMEM>>>(mask);
    k_finish<<<B_ROWS, 128>>>(out);
}

// round 12
// speedup vs baseline: 1.2609x; 1.2609x over previous
#include <cuda_runtime.h>
#include <cuda_fp16.h>
#include <cstdint>

#define IN_DIM  256
#define OUT_DIM 128
#define B_ROWS  4096
#define N_COLS  8192
#define ALPHA   0.2f
#define NSPLIT  8
#define NCHUNK  (N_COLS / NSPLIT)  // 1024 n per CTA
#define KT      32                 // n per K-tile
#define NT      (NCHUNK / KT)      // 32 tiles
#define NWORDS  (N_COLS / 32)      // 256 mask words per row

// ---------------- device scratch (static, allocation-free) ----------------
__device__ __align__(16) __half g_hb[N_COLS * OUT_DIM]; // [8192 n][128 f] fp16
__device__ float g_s2[N_COLS];
__device__ float g_p[N_COLS];
__device__ float g_q[N_COLS];
__device__ float g_t[B_ROWS];   // -s1[b]
__device__ float g_P[B_ROWS];
__device__ float g_Q[B_ROWS];
__device__ unsigned int g_s2max_bits;
__device__ __align__(16) uint32_t g_mbits[B_ROWS * NWORDS];               // 4 MB
__device__ __align__(16) float g_part[(size_t)NSPLIT * B_ROWS * OUT_DIM]; // 16 MB

// ---------------- helpers ----------------
__device__ __forceinline__ uint32_t smem_u32(const void* p) {
    uint32_t a;
    asm("{ .reg .u64 t; cvta.to.shared.u64 t, %1; cvt.u32.u64 %0, t; }"
        : "=r"(a) : "l"(p));
    return a;
}
__device__ __forceinline__ void cpa16(uint32_t s, const void* g) {
    asm volatile("cp.async.cg.shared.global [%0], [%1], 16;" :: "r"(s), "l"(g));
}
__device__ __forceinline__ void sts32(uint32_t a, uint32_t v) {
    asm volatile("st.shared.b32 [%0], %1;" :: "r"(a), "r"(v));
}
__device__ __forceinline__ void ldsm4(uint32_t* r, uint32_t a) {
    asm volatile("ldmatrix.sync.aligned.m8n8.x4.shared.b16 {%0,%1,%2,%3}, [%4];"
                 : "=r"(r[0]), "=r"(r[1]), "=r"(r[2]), "=r"(r[3]) : "r"(a));
}
__device__ __forceinline__ void ldsm4t(uint32_t* r, uint32_t a) {
    asm volatile("ldmatrix.sync.aligned.m8n8.x4.trans.shared.b16 {%0,%1,%2,%3}, [%4];"
                 : "=r"(r[0]), "=r"(r[1]), "=r"(r[2]), "=r"(r[3]) : "r"(a));
}
__device__ __forceinline__ void mma_f16(float* d, const uint32_t* a,
                                        uint32_t b0, uint32_t b1) {
    asm volatile(
        "mma.sync.aligned.m16n8k16.row.col.f32.f16.f16.f32 "
        "{%0,%1,%2,%3},{%4,%5,%6,%7},{%8,%9},{%0,%1,%2,%3};"
        : "+f"(d[0]), "+f"(d[1]), "+f"(d[2]), "+f"(d[3])
        : "r"(a[0]), "r"(a[1]), "r"(a[2]), "r"(a[3]), "r"(b0), "r"(b1));
}
__device__ __forceinline__ unsigned int f2key(float f) {
    int i = __float_as_int(f);
    return (i >= 0) ? ((unsigned)i ^ 0x80000000u) : ~(unsigned)i;
}
__device__ __forceinline__ float key2f(unsigned int k) {
    int i = (k & 0x80000000u) ? (int)(k ^ 0x80000000u) : (int)~k;
    return __int_as_float(i);
}

// ---------------- K0: k_pack — bit-pack the mask (streaming) ----------------
// Warp processes 1024 consecutive flat elements: coalesced LDG + ballot.
__global__ __launch_bounds__(256) void k_pack(const int* __restrict__ mask) {
    int cid = blockIdx.x * 8 + (threadIdx.x >> 5);   // chunk of 1024
    int lane = threadIdx.x & 31;
    const int* src = mask + (size_t)cid * 1024;
    uint32_t w = 0;
#pragma unroll
    for (int j = 0; j < 32; j++) {
        int v = src[j * 32 + lane];
        unsigned bal = __ballot_sync(0xffffffffu, v != 0);
        if (lane == j) w = bal;
    }
    g_mbits[(size_t)cid * 32 + lane] = w;
}

// ---------------- K1: k_prep — Wa1 (local), s1 -> g_t ----------------
__global__ __launch_bounds__(256) void k_prep(const float* __restrict__ gf,
                                              const int* __restrict__ nodes,
                                              const float* __restrict__ W,
                                              const float* __restrict__ a1) {
    __shared__ float sWa1[IN_DIM];
    int t = threadIdx.x, lane = t & 31, wid = t >> 5;
    if (blockIdx.x == 0 && t == 0) g_s2max_bits = 0u;
    {
        const float* row = W + t * OUT_DIM;
        float s = 0.f;
#pragma unroll 8
        for (int c = 0; c < OUT_DIM; c++) s += row[c] * a1[c];
        sWa1[t] = s;
    }
    __syncthreads();
#pragma unroll
    for (int rr = 0; rr < 4; rr++) {
        int b = blockIdx.x * 32 + wid * 4 + rr;
        const float* row = gf + (size_t)nodes[b] * IN_DIM;
        float s = 0.f;
#pragma unroll
        for (int k = lane; k < IN_DIM; k += 32) s += row[k] * sWa1[k];
#pragma unroll
        for (int o = 16; o; o >>= 1) s += __shfl_xor_sync(0xffffffffu, s, o);
        if (lane == 0) g_t[b] = -s;
    }
}

// ---------------- K2: k_hneigh — pipelined h = gf[un]@W; s2, max ----------
__global__ __launch_bounds__(256) void k_hneigh(
    const float* __restrict__ gf, const int* __restrict__ un,
    const float* __restrict__ W, const float* __restrict__ a2) {
    __shared__ __align__(16) float As[2][32][36];
    __shared__ __align__(16) float Ws[2][32][132];
    int t = threadIdx.x, lane = t & 31, wid = t >> 5;
    int r0 = blockIdx.x * 32;

    const int arow = t >> 3, ach = t & 7;
    const float* asrc = gf + (size_t)un[r0 + arow] * IN_DIM + ach * 4;
    uint32_t adst[2] = {smem_u32(&As[0][arow][ach * 4]),
                        smem_u32(&As[1][arow][ach * 4])};
    uint32_t wdst[2][4];
    const float* wsrc[4];
#pragma unroll
    for (int u = 0; u < 4; u++) {
        int idx = t * 4 + u, wrow = idx >> 5, wch = idx & 31;
        wsrc[u] = W + (size_t)wrow * OUT_DIM + wch * 4;
        wdst[0][u] = smem_u32(&Ws[0][wrow][wch * 4]);
        wdst[1][u] = smem_u32(&Ws[1][wrow][wch * 4]);
    }

    cpa16(adst[0], asrc);
#pragma unroll
    for (int u = 0; u < 4; u++) cpa16(wdst[0][u], wsrc[u]);
    asm volatile("cp.async.commit_group;");

    float acc[4][4] = {};
    for (int kb = 0; kb < 8; kb++) {
        const int cur = kb & 1;
        if (kb + 1 < 8) {
            cpa16(adst[cur ^ 1], asrc + (kb + 1) * 32);
#pragma unroll
            for (int u = 0; u < 4; u++)
                cpa16(wdst[cur ^ 1][u], wsrc[u] + (size_t)(kb + 1) * 32 * OUT_DIM);
            asm volatile("cp.async.commit_group;");
            asm volatile("cp.async.wait_group 1;");
        } else {
            asm volatile("cp.async.wait_group 0;");
        }
        __syncthreads();
#pragma unroll
        for (int kk = 0; kk < 32; kk++) {
            float4 wv = *(const float4*)&Ws[cur][kk][4 * lane];
            float wvv[4] = {wv.x, wv.y, wv.z, wv.w};
            float av[4];
#pragma unroll
            for (int i = 0; i < 4; i++) av[i] = As[cur][wid + 8 * i][kk];
#pragma unroll
            for (int i = 0; i < 4; i++)
#pragma unroll
                for (int c = 0; c < 4; c++) acc[i][c] += av[i] * wvv[c];
        }
        __syncthreads();
    }

    float4 a2v = *(const float4*)&a2[4 * lane];
    float wmax = -1e30f;
#pragma unroll
    for (int i = 0; i < 4; i++) {
        int r = r0 + wid + 8 * i;
        float part = acc[i][0] * a2v.x + acc[i][1] * a2v.y +
                     acc[i][2] * a2v.z + acc[i][3] * a2v.w;
#pragma unroll
        for (int o = 16; o; o >>= 1) part += __shfl_xor_sync(0xffffffffu, part, o);
        if (lane == 0) {
            g_s2[r] = part;
            wmax = fmaxf(wmax, part);
        }
        __half2 h01 = __floats2half2_rn(acc[i][0], acc[i][1]);
        __half2 h23 = __floats2half2_rn(acc[i][2], acc[i][3]);
        __half2* dst = (__half2*)(g_hb + (size_t)r * OUT_DIM + 4 * lane);
        dst[0] = h01;
        dst[1] = h23;
    }
    if (lane == 0) atomicMax(&g_s2max_bits, f2key(wmax));
}

// ---------------- K2b: k_pq — p/q per n, P/Q per row (true S2max) ----------
__global__ __launch_bounds__(256) void k_pq() {
    const float M = key2f(g_s2max_bits);
    int idx = blockIdx.x * 256 + threadIdx.x;
    if (idx < N_COLS) {
        float d = g_s2[idx] - M;
        g_p[idx] = expf(d);
        g_q[idx] = expf(ALPHA * d);
    } else {
        int b = idx - N_COLS;
        float s1 = -g_t[b];
        float v = s1 + M;
        float mh = fmaxf(v, ALPHA * v);
        g_P[b] = expf(v - mh);
        g_Q[b] = expf(ALPHA * v - mh);
    }
}

// ---------------- K3: k_main — pipelined HMMA weighted sum -----------------
// CTA 256 thr (8 warps), tile 128b x 128f (R10 shape), n-chunk 1024, 32 tiles.
// MMA warp grid: bwarp = wid>>1 (4 x 32b), fwarp = wid&1 (2 x 64f); 64 acc.
// Mask from g_mbits: ONE broadcast LDG.32 word/warp/tile + shfl to rows.
// Rings: Wt x3 (128x80B), Ht x3 (32x272B); ONE __syncthreads per tile.
// iter t: stage(t+2)->regs | wgen(t+1)->Wt[(t+1)%3] | wait h(t) | sync |
//         commit h(t+2)->Ht[(t+2)%3] | MMA(t).
__global__ __launch_bounds__(256, 2) void k_main() {
    extern __shared__ __align__(16) char dsm[];
    const uint32_t sb = smem_u32(dsm);
    const uint32_t Wt0 = sb;               // + k*10240, k<3
    const uint32_t Ht0 = sb + 30720;       // + k*8704,  k<3
    float* sT = (float*)(dsm + 56832);
    float* sP = sT + 128;
    float* sQ = sP + 128;

    const int tid = threadIdx.x, lane = tid & 31, wid = tid >> 5;
    const int qr = lane >> 2, qc = lane & 3;
    const int b0w = (wid >> 1) * 32, f0w = (wid & 1) * 64;
    const int gb0 = blockIdx.x * 128;
    const int nbase = blockIdx.y * NCHUNK;

    if (tid < 128) {
        sT[tid] = g_t[gb0 + tid];
        sP[tid] = g_P[gb0 + tid];
        sQ[tid] = g_Q[gb0 + tid];
    }

    // wgen mapping: warp owns rows [wid*16, wid*16+16); lane half bsub -> 8
    // rows, np = n-pair within tile.
    const int bsub = lane >> 4, np = lane & 15;
    const int r0w = wid * 16;
    const uint32_t wg0 = (uint32_t)(r0w + bsub * 8) * 80 + np * 4;

    // mask word pointer: lane (l&15) holds word for row r0w + (l&15)
    const uint32_t* mwp =
        g_mbits + (size_t)(gb0 + r0w + (lane & 15)) * NWORDS + blockIdx.y * 32;

    // h cp.async: row = tid>>3, 8 threads x 32B cover the 256B row
    const int hrow = tid >> 3, hc8 = tid & 7;
    const uint32_t hst = (uint32_t)hrow * 272 + hc8 * 32;
    const __half* hsrc = g_hb + (size_t)(nbase + hrow) * OUT_DIM + hc8 * 16;

    // ldmatrix per-lane offsets
    const uint32_t lrow = (lane & 7) + ((lane >> 3) & 1) * 8;
    const uint32_t akoff = ((lane >> 4) & 1) * 16;
    const uint32_t arow_off = lrow * 80 + akoff;
    const uint32_t brow_off = lrow * 272 + akoff;

    // register staging sets: tile k -> set[k&1]
    uint32_t mw[2];
    float2 pp[2], qq[2], ss[2];
#pragma unroll
    for (int k = 0; k < 2; k++) {
        mw[k] = mwp[k];
        int n0 = nbase + k * KT + 2 * np;
        pp[k] = *(const float2*)&g_p[n0];
        qq[k] = *(const float2*)&g_q[n0];
        ss[k] = *(const float2*)&g_s2[n0];
    }
    // h(0), h(1) in flight
    cpa16(Ht0 + hst, hsrc);
    cpa16(Ht0 + hst + 16, hsrc + 8);
    asm volatile("cp.async.commit_group;");
    cpa16(Ht0 + 8704 + hst, hsrc + KT * OUT_DIM);
    cpa16(Ht0 + 8704 + hst + 16, hsrc + KT * OUT_DIM + 8);
    asm volatile("cp.async.commit_group;");

    float d[2][8][4];
#pragma unroll
    for (int mb = 0; mb < 2; mb++)
#pragma unroll
        for (int fb = 0; fb < 8; fb++)
#pragma unroll
            for (int c = 0; c < 4; c++) d[mb][fb][c] = 0.f;

    __syncthreads();  // sT/sP/sQ visible

    // wgen(0) -> Wt[0]
    {
        uint32_t wa = Wt0 + wg0;
        uint32_t mr = mw[0];
#pragma unroll
        for (int i = 0; i < 8; i++) {
            int b = r0w + bsub * 8 + i;
            uint32_t mword = __shfl_sync(0xffffffffu, mr, bsub * 8 + i);
            float w0 = 0.f, w1 = 0.f;
            if ((mword >> (2 * np)) & 1)
                w0 = (ss[0].x >= sT[b]) ? sP[b] * pp[0].x : sQ[b] * qq[0].x;
            if ((mword >> (2 * np)) & 2)
                w1 = (ss[0].y >= sT[b]) ? sP[b] * pp[0].y : sQ[b] * qq[0].y;
            __half2 h2 = __floats2half2_rn(w0, w1);
            sts32(wa, *(uint32_t*)&h2);
            wa += 80;
        }
    }

    for (int t = 0; t < NT; t++) {
        // stage tile t+2 into set[t&1]
        if (t + 2 < NT) {
            mw[t & 1] = mwp[t + 2];
            int n0 = nbase + (t + 2) * KT + 2 * np;
            pp[t & 1] = *(const float2*)&g_p[n0];
            qq[t & 1] = *(const float2*)&g_q[n0];
            ss[t & 1] = *(const float2*)&g_s2[n0];
        }
        // wgen(t+1) from set[(t+1)&1] -> Wt[(t+1)%3]
        if (t + 1 < NT) {
            const int s = (t + 1) & 1;
            uint32_t wa = Wt0 + ((t + 1) % 3) * 10240 + wg0;
            uint32_t mr = mw[s];
#pragma unroll
            for (int i = 0; i < 8; i++) {
                int b = r0w + bsub * 8 + i;
                uint32_t mword = __shfl_sync(0xffffffffu, mr, bsub * 8 + i);
                float w0 = 0.f, w1 = 0.f;
                if ((mword >> (2 * np)) & 1)
                    w0 = (ss[s].x >= sT[b]) ? sP[b] * pp[s].x : sQ[b] * qq[s].x;
                if ((mword >> (2 * np)) & 2)
                    w1 = (ss[s].y >= sT[b]) ? sP[b] * pp[s].y : sQ[b] * qq[s].y;
                __half2 h2 = __floats2half2_rn(w0, w1);
                sts32(wa, *(uint32_t*)&h2);
                wa += 80;
            }
        }
        // ensure h(t) arrived (FIFO: <=1 pending => only h(t+1) may pend)
        if (t + 1 < NT) asm volatile("cp.async.wait_group 1;");
        else            asm volatile("cp.async.wait_group 0;");
        __syncthreads();

        // prefetch h(t+2) -> Ht[(t+2)%3] (last reader MMA(t-1) is pre-sync)
        if (t + 2 < NT) {
            uint32_t hd = Ht0 + ((t + 2) % 3) * 8704 + hst;
            const __half* src = hsrc + (t + 2) * KT * OUT_DIM;
            cpa16(hd, src);
            cpa16(hd + 16, src + 8);
            asm volatile("cp.async.commit_group;");
        }

        // MMA(t): Wt[t%3], Ht[t%3]; 2j x (2 A-LDSM + 4 B-LDSM.t + 16 HMMA)
        const uint32_t Wb = Wt0 + (t % 3) * 10240 + b0w * 80 + arow_off;
        const uint32_t Hb = Ht0 + (t % 3) * 8704 + f0w * 2 + brow_off;
#pragma unroll
        for (int j = 0; j < 2; j++) {
            uint32_t a0[4], a1[4];
            ldsm4(a0, Wb + j * 32);
            ldsm4(a1, Wb + j * 32 + 16 * 80);
#pragma unroll
            for (int P = 0; P < 4; P++) {
                uint32_t b4[4];
                ldsm4t(b4, Hb + j * 4352 + P * 32);
                mma_f16(d[0][2 * P], a0, b4[0], b4[1]);
                mma_f16(d[1][2 * P], a1, b4[0], b4[1]);
                mma_f16(d[0][2 * P + 1], a0, b4[2], b4[3]);
                mma_f16(d[1][2 * P + 1], a1, b4[2], b4[3]);
            }
        }
    }

    // epilogue: write partials (R10-validated mapping)
    float* pbase = g_part + (size_t)blockIdx.y * B_ROWS * OUT_DIM;
#pragma unroll
    for (int mb = 0; mb < 2; mb++) {
        int br = gb0 + b0w + mb * 16 + qr;
#pragma unroll
        for (int fb = 0; fb < 8; fb++) {
            int f = f0w + fb * 8 + qc * 2;
            float* p0 = pbase + (size_t)br * OUT_DIM + f;
            *(float2*)p0 = make_float2(d[mb][fb][0], d[mb][fb][1]);
            *(float2*)(p0 + 8 * OUT_DIM) = make_float2(d[mb][fb][2], d[mb][fb][3]);
        }
    }
}

// ---------------- K4: reduce partials + L2 normalize ----------------
__global__ __launch_bounds__(128) void k_finish(float* __restrict__ out) {
    __shared__ float red[4];
    int b = blockIdx.x, f = threadIdx.x;
    float s = 0.f;
#pragma unroll
    for (int k = 0; k < NSPLIT; k++)
        s += g_part[((size_t)k * B_ROWS + b) * OUT_DIM + f];
    float ss = s * s;
#pragma unroll
    for (int o = 16; o; o >>= 1) ss += __shfl_xor_sync(0xffffffffu, ss, o);
    if ((f & 31) == 0) red[f >> 5] = ss;
    __syncthreads();
    float tot = red[0] + red[1] + red[2] + red[3];
    out[b * OUT_DIM + f] = s / fmaxf(sqrtf(tot), 1e-12f);
}

// ---------------- launch ----------------
extern "C" void kernel_launch(void* const* d_in, const int* in_sizes, int n_in,
                              void* d_out, int out_size) {
    const float* gf    = (const float*)d_in[0];  // [100000, 256]
    const int*   nodes = (const int*)d_in[1];    // [4096]
    const int*   un    = (const int*)d_in[2];    // [8192]
    const int*   mask  = (const int*)d_in[3];    // [4096, 8192]
    const float* W     = (const float*)d_in[4];  // [256, 128]
    const float* a1    = (const float*)d_in[5];  // [128]
    const float* a2    = (const float*)d_in[6];  // [128]
    float* out = (float*)d_out;                  // [4096, 128]

    static int smem_set = 0;
    const int SMEM = 56832 + 3 * 128 * 4;  // 3xWt + 3xHt + sT/sP/sQ = 58368
    if (!smem_set) {
        cudaFuncSetAttribute(k_main, cudaFuncAttributeMaxDynamicSharedMemorySize, SMEM);
        smem_set = 1;
    }

    k_pack<<<(B_ROWS * N_COLS) / (1024 * 8), 256>>>(mask);
    k_prep<<<B_ROWS / 32, 256>>>(gf, nodes, W, a1);
    k_hneigh<<<N_COLS / 32, 256>>>(gf, un, W, a2);
    k_pq<<<(N_COLS + B_ROWS) / 256, 256>>>();
    k_main<<<dim3(B_ROWS / 128, NSPLIT), 256, SMEM>>>();
    k_finish<<<B_ROWS, 128>>>(out);
}

// round 13
// speedup vs baseline: 1.7598x; 1.3957x over previous
#include <cuda_runtime.h>
#include <cuda_fp16.h>
#include <cstdint>

#define IN_DIM  256
#define OUT_DIM 128
#define B_ROWS  4096
#define N_COLS  8192
#define ALPHA   0.2f
#define NSPLIT  8
#define NCHUNK  (N_COLS / NSPLIT)  // 1024 n per CTA
#define KT      32                 // n per K-tile
#define NT      (NCHUNK / KT)      // 32 tiles

// ---------------- device scratch (static, allocation-free) ----------------
__device__ __align__(16) __half g_hb[N_COLS * OUT_DIM];          // 2 MB
__device__ __align__(16) __half g_w[(size_t)B_ROWS * N_COLS];    // 64 MB
__device__ float g_s2[N_COLS];
__device__ float g_p[N_COLS];
__device__ float g_q[N_COLS];
__device__ float g_t[B_ROWS];   // -s1[b]
__device__ float g_P[B_ROWS];
__device__ float g_Q[B_ROWS];
__device__ unsigned int g_s2max_bits;
__device__ __align__(16) float g_part[(size_t)NSPLIT * B_ROWS * OUT_DIM]; // 16 MB

// ---------------- helpers ----------------
__device__ __forceinline__ uint32_t smem_u32(const void* p) {
    uint32_t a;
    asm("{ .reg .u64 t; cvta.to.shared.u64 t, %1; cvt.u32.u64 %0, t; }"
        : "=r"(a) : "l"(p));
    return a;
}
__device__ __forceinline__ void cpa16(uint32_t s, const void* g) {
    asm volatile("cp.async.cg.shared.global [%0], [%1], 16;" :: "r"(s), "l"(g));
}
__device__ __forceinline__ void ldsm4(uint32_t* r, uint32_t a) {
    asm volatile("ldmatrix.sync.aligned.m8n8.x4.shared.b16 {%0,%1,%2,%3}, [%4];"
                 : "=r"(r[0]), "=r"(r[1]), "=r"(r[2]), "=r"(r[3]) : "r"(a));
}
__device__ __forceinline__ void ldsm4t(uint32_t* r, uint32_t a) {
    asm volatile("ldmatrix.sync.aligned.m8n8.x4.trans.shared.b16 {%0,%1,%2,%3}, [%4];"
                 : "=r"(r[0]), "=r"(r[1]), "=r"(r[2]), "=r"(r[3]) : "r"(a));
}
__device__ __forceinline__ void mma_f16(float* d, const uint32_t* a,
                                        uint32_t b0, uint32_t b1) {
    asm volatile(
        "mma.sync.aligned.m16n8k16.row.col.f32.f16.f16.f32 "
        "{%0,%1,%2,%3},{%4,%5,%6,%7},{%8,%9},{%0,%1,%2,%3};"
        : "+f"(d[0]), "+f"(d[1]), "+f"(d[2]), "+f"(d[3])
        : "r"(a[0]), "r"(a[1]), "r"(a[2]), "r"(a[3]), "r"(b0), "r"(b1));
}
__device__ __forceinline__ unsigned int f2key(float f) {
    int i = __float_as_int(f);
    return (i >= 0) ? ((unsigned)i ^ 0x80000000u) : ~(unsigned)i;
}
__device__ __forceinline__ float key2f(unsigned int k) {
    int i = (k & 0x80000000u) ? (int)(k ^ 0x80000000u) : (int)~k;
    return __int_as_float(i);
}

// ---------------- K1: k_prep — Wa1 (local), s1 -> g_t ----------------
__global__ __launch_bounds__(256) void k_prep(const float* __restrict__ gf,
                                              const int* __restrict__ nodes,
                                              const float* __restrict__ W,
                                              const float* __restrict__ a1) {
    __shared__ float sWa1[IN_DIM];
    int t = threadIdx.x, lane = t & 31, wid = t >> 5;
    if (blockIdx.x == 0 && t == 0) g_s2max_bits = 0u;
    {
        const float* row = W + t * OUT_DIM;
        float s = 0.f;
#pragma unroll 8
        for (int c = 0; c < OUT_DIM; c++) s += row[c] * a1[c];
        sWa1[t] = s;
    }
    __syncthreads();
#pragma unroll
    for (int rr = 0; rr < 4; rr++) {
        int b = blockIdx.x * 32 + wid * 4 + rr;
        const float* row = gf + (size_t)nodes[b] * IN_DIM;
        float s = 0.f;
#pragma unroll
        for (int k = lane; k < IN_DIM; k += 32) s += row[k] * sWa1[k];
#pragma unroll
        for (int o = 16; o; o >>= 1) s += __shfl_xor_sync(0xffffffffu, s, o);
        if (lane == 0) g_t[b] = -s;
    }
}

// ---------------- K2: k_hneigh — pipelined h = gf[un]@W; s2, max ----------
__global__ __launch_bounds__(256) void k_hneigh(
    const float* __restrict__ gf, const int* __restrict__ un,
    const float* __restrict__ W, const float* __restrict__ a2) {
    __shared__ __align__(16) float As[2][32][36];
    __shared__ __align__(16) float Ws[2][32][132];
    int t = threadIdx.x, lane = t & 31, wid = t >> 5;
    int r0 = blockIdx.x * 32;

    const int arow = t >> 3, ach = t & 7;
    const float* asrc = gf + (size_t)un[r0 + arow] * IN_DIM + ach * 4;
    uint32_t adst[2] = {smem_u32(&As[0][arow][ach * 4]),
                        smem_u32(&As[1][arow][ach * 4])};
    uint32_t wdst[2][4];
    const float* wsrc[4];
#pragma unroll
    for (int u = 0; u < 4; u++) {
        int idx = t * 4 + u, wrow = idx >> 5, wch = idx & 31;
        wsrc[u] = W + (size_t)wrow * OUT_DIM + wch * 4;
        wdst[0][u] = smem_u32(&Ws[0][wrow][wch * 4]);
        wdst[1][u] = smem_u32(&Ws[1][wrow][wch * 4]);
    }

    cpa16(adst[0], asrc);
#pragma unroll
    for (int u = 0; u < 4; u++) cpa16(wdst[0][u], wsrc[u]);
    asm volatile("cp.async.commit_group;");

    float acc[4][4] = {};
    for (int kb = 0; kb < 8; kb++) {
        const int cur = kb & 1;
        if (kb + 1 < 8) {
            cpa16(adst[cur ^ 1], asrc + (kb + 1) * 32);
#pragma unroll
            for (int u = 0; u < 4; u++)
                cpa16(wdst[cur ^ 1][u], wsrc[u] + (size_t)(kb + 1) * 32 * OUT_DIM);
            asm volatile("cp.async.commit_group;");
            asm volatile("cp.async.wait_group 1;");
        } else {
            asm volatile("cp.async.wait_group 0;");
        }
        __syncthreads();
#pragma unroll
        for (int kk = 0; kk < 32; kk++) {
            float4 wv = *(const float4*)&Ws[cur][kk][4 * lane];
            float wvv[4] = {wv.x, wv.y, wv.z, wv.w};
            float av[4];
#pragma unroll
            for (int i = 0; i < 4; i++) av[i] = As[cur][wid + 8 * i][kk];
#pragma unroll
            for (int i = 0; i < 4; i++)
#pragma unroll
                for (int c = 0; c < 4; c++) acc[i][c] += av[i] * wvv[c];
        }
        __syncthreads();
    }

    float4 a2v = *(const float4*)&a2[4 * lane];
    float wmax = -1e30f;
#pragma unroll
    for (int i = 0; i < 4; i++) {
        int r = r0 + wid + 8 * i;
        float part = acc[i][0] * a2v.x + acc[i][1] * a2v.y +
                     acc[i][2] * a2v.z + acc[i][3] * a2v.w;
#pragma unroll
        for (int o = 16; o; o >>= 1) part += __shfl_xor_sync(0xffffffffu, part, o);
        if (lane == 0) {
            g_s2[r] = part;
            wmax = fmaxf(wmax, part);
        }
        __half2 h01 = __floats2half2_rn(acc[i][0], acc[i][1]);
        __half2 h23 = __floats2half2_rn(acc[i][2], acc[i][3]);
        __half2* dst = (__half2*)(g_hb + (size_t)r * OUT_DIM + 4 * lane);
        dst[0] = h01;
        dst[1] = h23;
    }
    if (lane == 0) atomicMax(&g_s2max_bits, f2key(wmax));
}

// ---------------- K2b: k_pq — p/q per n, P/Q per row (true S2max) ----------
__global__ __launch_bounds__(256) void k_pq() {
    const float M = key2f(g_s2max_bits);
    int idx = blockIdx.x * 256 + threadIdx.x;
    if (idx < N_COLS) {
        float d = g_s2[idx] - M;
        g_p[idx] = expf(d);
        g_q[idx] = expf(ALPHA * d);
    } else {
        int b = idx - N_COLS;
        float s1 = -g_t[b];
        float v = s1 + M;
        float mh = fmaxf(v, ALPHA * v);
        g_P[b] = expf(v - mh);
        g_Q[b] = expf(ALPHA * v - mh);
    }
}

// ---------------- K3: k_wgen — materialize w[b][n] fp16 (streaming) --------
// block: n-chunk of 1024 (x, 8) x row-group of 64 (y, 64); thread -> 4 n.
// p/q/s2 live in registers across the row loop; mask streamed once.
__global__ __launch_bounds__(256) void k_wgen(const int* __restrict__ mask) {
    const int n0 = blockIdx.x * 1024 + threadIdx.x * 4;
    const int b0 = blockIdx.y * 64;
    const float4 p4 = *(const float4*)&g_p[n0];
    const float4 q4 = *(const float4*)&g_q[n0];
    const float4 s4 = *(const float4*)&g_s2[n0];
    const int* mp = mask + (size_t)b0 * N_COLS + n0;
    __half* wp = g_w + (size_t)b0 * N_COLS + n0;
#pragma unroll 2
    for (int r = 0; r < 64; r++) {
        const int b = b0 + r;
        const float T = g_t[b], P = g_P[b], Q = g_Q[b];
        int4 m = *(const int4*)mp;
        float w0 = m.x ? ((s4.x >= T) ? P * p4.x : Q * q4.x) : 0.f;
        float w1 = m.y ? ((s4.y >= T) ? P * p4.y : Q * q4.y) : 0.f;
        float w2 = m.z ? ((s4.z >= T) ? P * p4.z : Q * q4.z) : 0.f;
        float w3 = m.w ? ((s4.w >= T) ? P * p4.w : Q * q4.w) : 0.f;
        __half2 h01 = __floats2half2_rn(w0, w1);
        __half2 h23 = __floats2half2_rn(w2, w3);
        uint2 st = make_uint2(*(uint32_t*)&h01, *(uint32_t*)&h23);
        *(uint2*)wp = st;
        mp += N_COLS;
        wp += N_COLS;
    }
}

// ---------------- K4: k_gemm — pure fp16 HMMA GEMM out += w @ h ------------
// CTA 256 thr (8 warps), tile 128b x 128f, n-chunk 1024, 32 K-tiles of 32 n.
// A = w tile [128 b][32 n] rows 80B; B = h tile [32 n][128 f] rows 272B.
// Both operands cp.async, 3-ring each, ONE __syncthreads per tile.
// iter t: wait h/w(t) | sync | commit (t+2) | MMA(t).
__global__ __launch_bounds__(256, 2) void k_gemm() {
    extern __shared__ __align__(16) char dsm[];
    const uint32_t sb = smem_u32(dsm);
    const uint32_t Wt0 = sb;               // + k*10240, k<3 (128 x 80B)
    const uint32_t Ht0 = sb + 30720;       // + k*8704,  k<3 (32 x 272B)

    const int tid = threadIdx.x, lane = tid & 31, wid = tid >> 5;
    const int qr = lane >> 2, qc = lane & 3;
    const int b0w = (wid >> 1) * 32, f0w = (wid & 1) * 64;
    const int gb0 = blockIdx.x * 128;
    const int nbase = blockIdx.y * NCHUNK;

    // A cp.async: row = tid>>1, 32B half
    const int ar = tid >> 1, ah = tid & 1;
    const uint32_t ast = (uint32_t)ar * 80 + ah * 32;
    const __half* asrc = g_w + (size_t)(gb0 + ar) * N_COLS + nbase + ah * 16;

    // B cp.async: row = tid>>3, 32B chunk
    const int hr = tid >> 3, hc = tid & 7;
    const uint32_t hst = (uint32_t)hr * 272 + hc * 32;
    const __half* hsrc = g_hb + (size_t)(nbase + hr) * OUT_DIM + hc * 16;

    // ldmatrix per-lane offsets (R10/R12-proven)
    const uint32_t lrow = (lane & 7) + ((lane >> 3) & 1) * 8;
    const uint32_t akoff = ((lane >> 4) & 1) * 16;
    const uint32_t arow_off = lrow * 80 + akoff;
    const uint32_t brow_off = lrow * 272 + akoff;

    // prologue: tiles 0, 1 in flight (one commit group per tile)
#pragma unroll
    for (int k = 0; k < 2; k++) {
        cpa16(Wt0 + k * 10240 + ast, asrc + k * KT);
        cpa16(Wt0 + k * 10240 + ast + 16, asrc + k * KT + 8);
        cpa16(Ht0 + k * 8704 + hst, hsrc + k * KT * OUT_DIM);
        cpa16(Ht0 + k * 8704 + hst + 16, hsrc + k * KT * OUT_DIM + 8);
        asm volatile("cp.async.commit_group;");
    }

    float d[2][8][4];
#pragma unroll
    for (int mb = 0; mb < 2; mb++)
#pragma unroll
        for (int fb = 0; fb < 8; fb++)
#pragma unroll
            for (int c = 0; c < 4; c++) d[mb][fb][c] = 0.f;

    for (int t = 0; t < NT; t++) {
        if (t + 1 < NT) asm volatile("cp.async.wait_group 1;");
        else            asm volatile("cp.async.wait_group 0;");
        __syncthreads();  // tile t complete for all threads; MMA(t-1) done

        // prefetch tile t+2 into ring slot (t+2)%3 (freed by MMA(t-1))
        if (t + 2 < NT) {
            const int k = (t + 2) % 3;
            cpa16(Wt0 + k * 10240 + ast, asrc + (t + 2) * KT);
            cpa16(Wt0 + k * 10240 + ast + 16, asrc + (t + 2) * KT + 8);
            cpa16(Ht0 + k * 8704 + hst, hsrc + (t + 2) * KT * OUT_DIM);
            cpa16(Ht0 + k * 8704 + hst + 16, hsrc + (t + 2) * KT * OUT_DIM + 8);
            asm volatile("cp.async.commit_group;");
        }

        // MMA(t): 2j x (2 A-LDSM + 4 B-LDSM.t + 16 HMMA)
        const uint32_t Wb = Wt0 + (t % 3) * 10240 + b0w * 80 + arow_off;
        const uint32_t Hb = Ht0 + (t % 3) * 8704 + f0w * 2 + brow_off;
#pragma unroll
        for (int j = 0; j < 2; j++) {
            uint32_t a0[4], a1[4];
            ldsm4(a0, Wb + j * 32);
            ldsm4(a1, Wb + j * 32 + 16 * 80);
#pragma unroll
            for (int P = 0; P < 4; P++) {
                uint32_t b4[4];
                ldsm4t(b4, Hb + j * 4352 + P * 32);
                mma_f16(d[0][2 * P], a0, b4[0], b4[1]);
                mma_f16(d[1][2 * P], a1, b4[0], b4[1]);
                mma_f16(d[0][2 * P + 1], a0, b4[2], b4[3]);
                mma_f16(d[1][2 * P + 1], a1, b4[2], b4[3]);
            }
        }
    }

    // epilogue: write partials (R10-validated mapping)
    float* pbase = g_part + (size_t)blockIdx.y * B_ROWS * OUT_DIM;
#pragma unroll
    for (int mb = 0; mb < 2; mb++) {
        int br = gb0 + b0w + mb * 16 + qr;
#pragma unroll
        for (int fb = 0; fb < 8; fb++) {
            int f = f0w + fb * 8 + qc * 2;
            float* p0 = pbase + (size_t)br * OUT_DIM + f;
            *(float2*)p0 = make_float2(d[mb][fb][0], d[mb][fb][1]);
            *(float2*)(p0 + 8 * OUT_DIM) = make_float2(d[mb][fb][2], d[mb][fb][3]);
        }
    }
}

// ---------------- K5: reduce partials + L2 normalize ----------------
__global__ __launch_bounds__(128) void k_finish(float* __restrict__ out) {
    __shared__ float red[4];
    int b = blockIdx.x, f = threadIdx.x;
    float s = 0.f;
#pragma unroll
    for (int k = 0; k < NSPLIT; k++)
        s += g_part[((size_t)k * B_ROWS + b) * OUT_DIM + f];
    float ss = s * s;
#pragma unroll
    for (int o = 16; o; o >>= 1) ss += __shfl_xor_sync(0xffffffffu, ss, o);
    if ((f & 31) == 0) red[f >> 5] = ss;
    __syncthreads();
    float tot = red[0] + red[1] + red[2] + red[3];
    out[b * OUT_DIM + f] = s / fmaxf(sqrtf(tot), 1e-12f);
}

// ---------------- launch ----------------
extern "C" void kernel_launch(void* const* d_in, const int* in_sizes, int n_in,
                              void* d_out, int out_size) {
    const float* gf    = (const float*)d_in[0];  // [100000, 256]
    const int*   nodes = (const int*)d_in[1];    // [4096]
    const int*   un    = (const int*)d_in[2];    // [8192]
    const int*   mask  = (const int*)d_in[3];    // [4096, 8192]
    const float* W     = (const float*)d_in[4];  // [256, 128]
    const float* a1    = (const float*)d_in[5];  // [128]
    const float* a2    = (const float*)d_in[6];  // [128]
    float* out = (float*)d_out;                  // [4096, 128]

    static int smem_set = 0;
    const int SMEM = 30720 + 3 * 8704;  // 3x Wt + 3x Ht = 56832
    if (!smem_set) {
        cudaFuncSetAttribute(k_gemm, cudaFuncAttributeMaxDynamicSharedMemorySize, SMEM);
        smem_set = 1;
    }

    k_prep<<<B_ROWS / 32, 256>>>(gf, nodes, W, a1);
    k_hneigh<<<N_COLS / 32, 256>>>(gf, un, W, a2);
    k_pq<<<(N_COLS + B_ROWS) / 256, 256>>>();
    k_wgen<<<dim3(N_COLS / 1024, B_ROWS / 64), 256>>>(mask);
    k_gemm<<<dim3(B_ROWS / 128, NSPLIT), 256, SMEM>>>();
    k_finish<<<B_ROWS, 128>>>(out);
}